// round 1
// baseline (speedup 1.0000x reference)
#include <cuda_runtime.h>
#include <cuda_bf16.h>

#define NN 50000
#define EE 800000
#define HD 128            // H*D
#define IN_DIM 256
#define NEG_SLOPE 0.2f
#define BN_EPS 1e-5f

// ---------------- scratch (device globals; no allocations allowed) -----------
__device__ float    g_h[NN * HD];       // projected features [N,128]
__device__ float    g_el[NN * 4];       // attn-left  per node per head
__device__ float    g_er[NN * 4];       // attn-right per node per head
__device__ unsigned g_m[NN * 4];        // segment max (order-encoded float)
__device__ float    g_s[NN * 4];        // segment sum of exp
__device__ float    g_ex[EE * 4];       // exp(e - m[dst]) per edge per head
__device__ float    g_rst[NN * HD];     // aggregated messages
__device__ float    g_sums[HD];
__device__ float    g_sumsq[HD];

// order-preserving float <-> uint for atomicMax
__device__ __forceinline__ unsigned fenc(float f) {
    unsigned i = __float_as_uint(f);
    return (i & 0x80000000u) ? ~i : (i | 0x80000000u);
}
__device__ __forceinline__ float fdec(unsigned u) {
    return (u & 0x80000000u) ? __uint_as_float(u & 0x7fffffffu)
                             : __uint_as_float(~u);
}

// ---------------- init: zero/seed all accumulators ---------------------------
__global__ void init_kernel() {
    int i = blockIdx.x * blockDim.x + threadIdx.x;   // exactly NN*HD threads
    g_rst[i] = 0.f;
    if (i < NN * 4) { g_m[i] = 0u; g_s[i] = 0.f; }   // 0 <= fenc(any finite)
    if (i < HD)     { g_sums[i] = 0.f; g_sumsq[i] = 0.f; }
}

// ---------------- GEMM h = x@W  +  el/er epilogue ----------------------------
// block: 128 threads (thread = output column; warp = head), 32 rows per block
__global__ void __launch_bounds__(128) gemm_kernel(
    const float* __restrict__ x, const float* __restrict__ W,
    const float* __restrict__ attn_l, const float* __restrict__ attn_r)
{
    __shared__ float xs[32 * IN_DIM];
    const int tid  = threadIdx.x;
    const int row0 = blockIdx.x * 32;

    float4* xsv = (float4*)xs;
    for (int i = tid; i < 32 * (IN_DIM / 4); i += 128) {
        int r  = i >> 6;                 // / (IN_DIM/4)
        int gr = row0 + r;
        float4 v = make_float4(0.f, 0.f, 0.f, 0.f);
        if (gr < NN) v = ((const float4*)x)[gr * (IN_DIM / 4) + (i & 63)];
        xsv[i] = v;
    }
    __syncthreads();

    float acc[32];
#pragma unroll
    for (int r = 0; r < 32; r++) acc[r] = 0.f;

#pragma unroll 4
    for (int k = 0; k < IN_DIM; k += 4) {
        float w0 = W[(k + 0) * HD + tid];
        float w1 = W[(k + 1) * HD + tid];
        float w2 = W[(k + 2) * HD + tid];
        float w3 = W[(k + 3) * HD + tid];
#pragma unroll
        for (int r = 0; r < 32; r++) {
            float4 xv = xsv[r * 64 + (k >> 2)];
            acc[r] = fmaf(xv.x, w0, acc[r]);
            acc[r] = fmaf(xv.y, w1, acc[r]);
            acc[r] = fmaf(xv.z, w2, acc[r]);
            acc[r] = fmaf(xv.w, w3, acc[r]);
        }
    }

    const int head = tid >> 5, lane = tid & 31;
    const float al = attn_l[head * 32 + lane];
    const float ar = attn_r[head * 32 + lane];
#pragma unroll
    for (int r = 0; r < 32; r++) {
        int gr = row0 + r;
        if (gr >= NN) break;
        g_h[gr * HD + tid] = acc[r];
        float lv = acc[r] * al, rv = acc[r] * ar;
#pragma unroll
        for (int o = 16; o > 0; o >>= 1) {
            lv += __shfl_xor_sync(0xffffffffu, lv, o);
            rv += __shfl_xor_sync(0xffffffffu, rv, o);
        }
        if (lane == 0) { g_el[gr * 4 + head] = lv; g_er[gr * 4 + head] = rv; }
    }
}

__device__ __forceinline__ void edge_e(int s, int d, float ev[4]) {
    float4 el = ((const float4*)g_el)[s];
    float4 er = ((const float4*)g_er)[d];
    ev[0] = el.x + er.x; ev[1] = el.y + er.y;
    ev[2] = el.z + er.z; ev[3] = el.w + er.w;
#pragma unroll
    for (int h = 0; h < 4; h++) ev[h] = ev[h] > 0.f ? ev[h] : NEG_SLOPE * ev[h];
}

// ---------------- edge pass A: segment max ----------------------------------
__global__ void edge_max_kernel(const int* __restrict__ src,
                                const int* __restrict__ dst)
{
    int e = blockIdx.x * blockDim.x + threadIdx.x;
    if (e >= EE) return;
    int s = src[e], d = dst[e];
    float ev[4]; edge_e(s, d, ev);
#pragma unroll
    for (int h = 0; h < 4; h++) atomicMax(&g_m[d * 4 + h], fenc(ev[h]));
}

// ---------------- edge pass B: exp + segment sum -----------------------------
__global__ void edge_exp_kernel(const int* __restrict__ src,
                                const int* __restrict__ dst)
{
    int e = blockIdx.x * blockDim.x + threadIdx.x;
    if (e >= EE) return;
    int s = src[e], d = dst[e];
    float ev[4]; edge_e(s, d, ev);
    float ex[4];
#pragma unroll
    for (int h = 0; h < 4; h++) {
        float m = fdec(g_m[d * 4 + h]);
        ex[h] = __expf(ev[h] - m);
        atomicAdd(&g_s[d * 4 + h], ex[h]);
    }
    ((float4*)g_ex)[e] = make_float4(ex[0], ex[1], ex[2], ex[3]);
}

// ---------------- edge pass C: weighted aggregation (warp per edge) ----------
__global__ void edge_agg_kernel(const int* __restrict__ src,
                                const int* __restrict__ dst)
{
    int w = (blockIdx.x * blockDim.x + threadIdx.x) >> 5;
    int lane = threadIdx.x & 31;
    if (w >= EE) return;
    int s = src[w], d = dst[w];
    int h = lane >> 3;                                  // 8 lanes per head
    float alpha = g_ex[w * 4 + h] / g_s[d * 4 + h];
    float4 hv = ((const float4*)g_h)[s * 32 + lane];
    float* p = &g_rst[d * HD + lane * 4];
    asm volatile("red.global.add.v4.f32 [%0], {%1,%2,%3,%4};"
                 :: "l"(p), "f"(hv.x * alpha), "f"(hv.y * alpha),
                    "f"(hv.z * alpha), "f"(hv.w * alpha)
                 : "memory");
}

// ---------------- BN stats ---------------------------------------------------
__global__ void bn_stats_kernel() {
    int c = threadIdx.x;                 // 128 threads = channels
    float s = 0.f, s2 = 0.f;
    for (int r = blockIdx.x; r < NN; r += gridDim.x) {
        float v = g_rst[r * HD + c];
        s += v; s2 += v * v;
    }
    atomicAdd(&g_sums[c], s);
    atomicAdd(&g_sumsq[c], s2);
}

// ---------------- BN normalize + ReLU ---------------------------------------
__global__ void bn_apply_kernel(const float* __restrict__ gamma,
                                const float* __restrict__ beta,
                                float* __restrict__ out)
{
    int i = blockIdx.x * blockDim.x + threadIdx.x;   // NN*HD threads
    int c = i & (HD - 1);
    const float inv_n = 1.f / (float)NN;
    float mean = g_sums[c] * inv_n;
    float var  = g_sumsq[c] * inv_n - mean * mean;
    float y = gamma[c] * (g_rst[i] - mean) * rsqrtf(var + BN_EPS) + beta[c];
    out[i] = y > 0.f ? y : 0.f;
}

// ---------------- launch -----------------------------------------------------
extern "C" void kernel_launch(void* const* d_in, const int* in_sizes, int n_in,
                              void* d_out, int out_size)
{
    const float* x      = (const float*)d_in[0];
    const int*   src    = (const int*)d_in[1];
    const int*   dst    = (const int*)d_in[2];
    const float* W      = (const float*)d_in[3];
    const float* attn_l = (const float*)d_in[4];
    const float* attn_r = (const float*)d_in[5];
    // d_in[6] = bias: cancels inside batch-norm (constant per-channel shift)
    const float* gamma  = (const float*)d_in[7];
    const float* beta   = (const float*)d_in[8];
    float* out = (float*)d_out;

    init_kernel<<<(NN * HD) / 256, 256>>>();
    gemm_kernel<<<(NN + 31) / 32, 128>>>(x, W, attn_l, attn_r);
    edge_max_kernel<<<(EE + 255) / 256, 256>>>(src, dst);
    edge_exp_kernel<<<(EE + 255) / 256, 256>>>(src, dst);
    edge_agg_kernel<<<(EE * 32) / 256, 256>>>(src, dst);
    bn_stats_kernel<<<512, 128>>>();
    bn_apply_kernel<<<(NN * HD) / 256, 256>>>(gamma, beta, out);
}

// round 3
// speedup vs baseline: 1.0763x; 1.0763x over previous
#include <cuda_runtime.h>
#include <cuda_bf16.h>

#define NN 50000
#define EE 800000
#define HD 128            // H*D
#define IN_DIM 256
#define NEG_SLOPE 0.2f
#define BN_EPS 1e-5f

// ---------------- scratch (device globals; no allocations allowed) -----------
__device__ float    g_h[NN * HD];       // projected features [N,128]
__device__ float    g_el[NN * 4];       // attn-left  per node per head
__device__ float    g_er[NN * 4];       // attn-right per node per head
__device__ unsigned g_cnt[NN];          // in-degree histogram
__device__ unsigned g_off[NN + 1];      // CSR offsets (by dst)
__device__ unsigned g_cur[NN];          // scatter cursors
__device__ int      g_esrc[EE];         // src node id per CSR slot
__device__ float    g_rst[NN * HD];     // aggregated messages
__device__ float    g_sums[HD];
__device__ float    g_sumsq[HD];

__device__ __forceinline__ float sel4(float4 v, int i) {
    float r = v.x;
    if (i == 1) r = v.y; else if (i == 2) r = v.z; else if (i == 3) r = v.w;
    return r;
}

// ---------------- zero accumulators ------------------------------------------
__global__ void zero_kernel() {
    int i = blockIdx.x * blockDim.x + threadIdx.x;
    if (i < NN) g_cnt[i] = 0u;
    if (i < HD) { g_sums[i] = 0.f; g_sumsq[i] = 0.f; }
}

// ---------------- GEMM h = x@W (register tiled) + el/er epilogue -------------
// BM=128, BN=128, BK=8; 256 threads; each thread computes an 8x8 tile.
__global__ void __launch_bounds__(256) gemm_kernel(
    const float* __restrict__ x, const float* __restrict__ W,
    const float* __restrict__ attn_l, const float* __restrict__ attn_r)
{
    __shared__ float xs[8][128];   // [k][m]
    __shared__ float ws[8][128];   // [k][n]
    const int tid  = threadIdx.x;
    const int row0 = blockIdx.x * 128;
    const int ty = tid >> 4, tx = tid & 15;        // 16x16 thread grid

    // load mapping
    const int lr = tid >> 1;            // x row within tile (0..127)
    const int lk = (tid & 1) * 4;       // k sub-offset {0,4}
    const int wk = tid >> 5;            // W k row (0..7)
    const int wc = (tid & 31) * 4;      // W col

    float acc[8][8];
#pragma unroll
    for (int i = 0; i < 8; i++)
#pragma unroll
        for (int j = 0; j < 8; j++) acc[i][j] = 0.f;

    for (int k0 = 0; k0 < IN_DIM; k0 += 8) {
        float4 xv = make_float4(0.f, 0.f, 0.f, 0.f);
        int gr = row0 + lr;
        if (gr < NN) xv = *(const float4*)&x[gr * IN_DIM + k0 + lk];
        xs[lk + 0][lr] = xv.x; xs[lk + 1][lr] = xv.y;
        xs[lk + 2][lr] = xv.z; xs[lk + 3][lr] = xv.w;
        *(float4*)&ws[wk][wc] = *(const float4*)&W[(k0 + wk) * HD + wc];
        __syncthreads();

#pragma unroll
        for (int k = 0; k < 8; k++) {
            float a[8], b[8];
            *(float4*)&a[0] = *(const float4*)&xs[k][ty * 8];
            *(float4*)&a[4] = *(const float4*)&xs[k][ty * 8 + 4];
            *(float4*)&b[0] = *(const float4*)&ws[k][tx * 8];
            *(float4*)&b[4] = *(const float4*)&ws[k][tx * 8 + 4];
#pragma unroll
            for (int i = 0; i < 8; i++)
#pragma unroll
                for (int j = 0; j < 8; j++)
                    acc[i][j] = fmaf(a[i], b[j], acc[i][j]);
        }
        __syncthreads();
    }

    // epilogue: store h, reduce el/er per (row, head)
    const int colb = tx * 8;
    const int hh   = tx >> 2;            // head of this column group
    float av_l[8], av_r[8];
#pragma unroll
    for (int j = 0; j < 8; j++) { av_l[j] = attn_l[colb + j]; av_r[j] = attn_r[colb + j]; }

#pragma unroll
    for (int i = 0; i < 8; i++) {
        int r = row0 + ty * 8 + i;
        bool valid = (r < NN);
        if (valid) {
            float4 h0 = make_float4(acc[i][0], acc[i][1], acc[i][2], acc[i][3]);
            float4 h1 = make_float4(acc[i][4], acc[i][5], acc[i][6], acc[i][7]);
            ((float4*)g_h)[r * 32 + tx * 2]     = h0;
            ((float4*)g_h)[r * 32 + tx * 2 + 1] = h1;
        }
        float pl = 0.f, pr = 0.f;
#pragma unroll
        for (int j = 0; j < 8; j++) {
            pl = fmaf(acc[i][j], av_l[j], pl);
            pr = fmaf(acc[i][j], av_r[j], pr);
        }
        // reduce over the 4 adjacent lanes that share this (row, head)
        pl += __shfl_xor_sync(0xffffffffu, pl, 1);
        pl += __shfl_xor_sync(0xffffffffu, pl, 2);
        pr += __shfl_xor_sync(0xffffffffu, pr, 1);
        pr += __shfl_xor_sync(0xffffffffu, pr, 2);
        if (valid && (tx & 3) == 0) {
            g_el[r * 4 + hh] = pl;
            g_er[r * 4 + hh] = pr;
        }
    }
}

// ---------------- CSR build: histogram ---------------------------------------
__global__ void hist_kernel(const int* __restrict__ dst) {
    int e = blockIdx.x * blockDim.x + threadIdx.x;
    if (e < EE) atomicAdd(&g_cnt[dst[e]], 1u);
}

// ---------------- CSR build: exclusive scan (single block) -------------------
__global__ void __launch_bounds__(1024) scan_kernel() {
    __shared__ unsigned sh[1024];
    const int T = 1024, CH = (NN + T - 1) / T;   // 49
    int t = threadIdx.x;
    int base = t * CH;

    unsigned s = 0;
    for (int i = 0; i < CH; i++) {
        int idx = base + i;
        if (idx < NN) s += g_cnt[idx];
    }
    sh[t] = s;
    __syncthreads();
    for (int off = 1; off < T; off <<= 1) {
        unsigned v = (t >= off) ? sh[t - off] : 0u;
        __syncthreads();
        sh[t] += v;
        __syncthreads();
    }
    unsigned run = sh[t] - s;     // exclusive prefix of this thread's chunk
    for (int i = 0; i < CH; i++) {
        int idx = base + i;
        if (idx < NN) {
            g_off[idx] = run;
            g_cur[idx] = run;
            run += g_cnt[idx];
        }
    }
    if (t == T - 1) g_off[NN] = run;
}

// ---------------- CSR build: scatter edge sources ----------------------------
__global__ void scatter_kernel(const int* __restrict__ src,
                               const int* __restrict__ dst) {
    int e = blockIdx.x * blockDim.x + threadIdx.x;
    if (e >= EE) return;
    int d = dst[e];
    unsigned pos = atomicAdd(&g_cur[d], 1u);
    g_esrc[pos] = src[e];
}

// ---------------- fused softmax + aggregation: one warp per dst node ---------
// rst[d] = (sum_e exp(leaky(el[s]+er[d])) * h[s]) / sum_e exp(...)
__global__ void __launch_bounds__(256) agg_kernel() {
    int gwarp = (blockIdx.x * 256 + threadIdx.x) >> 5;
    int l = threadIdx.x & 31;
    if (gwarp >= NN) return;
    const int d = gwarp;
    const int beg = (int)g_off[d], end = (int)g_off[d + 1];

    const float4 er4 = ((const float4*)g_er)[d];
    const int hh = l >> 3;                 // 8 lanes per head
    const float erc = sel4(er4, hh);

    float4 acc = make_float4(0.f, 0.f, 0.f, 0.f);
    float sumex = 0.f;

    int sn = (beg < end) ? __ldg(&g_esrc[beg]) : 0;
    for (int i = beg; i < end; i++) {
        int s = sn;
        if (i + 1 < end) sn = __ldg(&g_esrc[i + 1]);
        float4 el4 = ((const float4*)g_el)[s];
        float e = sel4(el4, hh) + erc;
        e = e > 0.f ? e : NEG_SLOPE * e;
        float ex = __expf(e);
        sumex += ex;
        float4 hv = ((const float4*)g_h)[s * 32 + l];
        acc.x = fmaf(ex, hv.x, acc.x);
        acc.y = fmaf(ex, hv.y, acc.y);
        acc.z = fmaf(ex, hv.z, acc.z);
        acc.w = fmaf(ex, hv.w, acc.w);
    }
    float inv = (sumex > 0.f) ? 1.f / sumex : 0.f;
    float4 o;
    o.x = acc.x * inv; o.y = acc.y * inv; o.z = acc.z * inv; o.w = acc.w * inv;
    ((float4*)g_rst)[d * 32 + l] = o;
}

// ---------------- BN stats ---------------------------------------------------
__global__ void bn_stats_kernel() {
    int c = threadIdx.x;                 // 128 threads = channels
    float s = 0.f, s2 = 0.f;
    for (int r = blockIdx.x; r < NN; r += gridDim.x) {
        float v = g_rst[r * HD + c];
        s += v; s2 += v * v;
    }
    atomicAdd(&g_sums[c], s);
    atomicAdd(&g_sumsq[c], s2);
}

// ---------------- BN normalize + ReLU ---------------------------------------
__global__ void bn_apply_kernel(const float* __restrict__ gamma,
                                const float* __restrict__ beta,
                                float* __restrict__ out)
{
    int i = blockIdx.x * blockDim.x + threadIdx.x;   // NN*HD threads
    int c = i & (HD - 1);
    const float inv_n = 1.f / (float)NN;
    float mean = g_sums[c] * inv_n;
    float var  = g_sumsq[c] * inv_n - mean * mean;
    float y = gamma[c] * (g_rst[i] - mean) * rsqrtf(var + BN_EPS) + beta[c];
    out[i] = y > 0.f ? y : 0.f;
}

// ---------------- launch -----------------------------------------------------
extern "C" void kernel_launch(void* const* d_in, const int* in_sizes, int n_in,
                              void* d_out, int out_size)
{
    const float* x      = (const float*)d_in[0];
    const int*   src    = (const int*)d_in[1];
    const int*   dst    = (const int*)d_in[2];
    const float* W      = (const float*)d_in[3];
    const float* attn_l = (const float*)d_in[4];
    const float* attn_r = (const float*)d_in[5];
    // d_in[6] = bias: constant per-channel shift, cancels inside batch-norm
    const float* gamma  = (const float*)d_in[7];
    const float* beta   = (const float*)d_in[8];
    float* out = (float*)d_out;

    zero_kernel<<<(NN + 255) / 256, 256>>>();
    gemm_kernel<<<(NN + 127) / 128, 256>>>(x, W, attn_l, attn_r);
    hist_kernel<<<(EE + 255) / 256, 256>>>(dst);
    scan_kernel<<<1, 1024>>>();
    scatter_kernel<<<(EE + 255) / 256, 256>>>(src, dst);
    agg_kernel<<<(NN * 32 + 255) / 256, 256>>>();
    bn_stats_kernel<<<512, 128>>>();
    bn_apply_kernel<<<(NN * HD) / 256, 256>>>(gamma, beta, out);
}

// round 4
// speedup vs baseline: 1.8392x; 1.7088x over previous
#include <cuda_runtime.h>
#include <cuda_bf16.h>

#define NN 50000
#define EE 800000
#define HD 128            // H*D
#define IN_DIM 256
#define NEG_SLOPE 0.2f
#define BN_EPS 1e-5f
#define NB 196            // ceil(NN/256) scan blocks

// ---------------- scratch (device globals; no allocations allowed) -----------
__device__ float    g_h[NN * HD];       // projected features [N,128]
__device__ float    g_el[NN * 4];       // attn-left  per node per head
__device__ float    g_er[NN * 4];       // attn-right per node per head
__device__ unsigned g_cnt[NN];          // in-degree histogram
__device__ unsigned g_off[NN + 1];      // CSR offsets (by dst)
__device__ unsigned g_cur[NN];          // scatter cursors
__device__ unsigned g_bsum[NB];         // per-block count sums
__device__ unsigned g_bpre[NB];         // exclusive prefix of block sums
__device__ int      g_esrc[EE];         // src node id per CSR slot
__device__ float    g_rst[NN * HD];     // aggregated messages
__device__ float    g_sums[HD];
__device__ float    g_sumsq[HD];

__device__ __forceinline__ float sel4(float4 v, int i) {
    float r = v.x;
    if (i == 1) r = v.y; else if (i == 2) r = v.z; else if (i == 3) r = v.w;
    return r;
}

__device__ __forceinline__ unsigned f2tf32(float f) {
    unsigned u;
    asm("cvt.rna.tf32.f32 %0, %1;" : "=r"(u) : "f"(f));
    return u;
}

__device__ __forceinline__ void mma_tf32(float4& c, const unsigned a[4],
                                         unsigned b0, unsigned b1) {
    asm volatile(
        "mma.sync.aligned.m16n8k8.row.col.f32.tf32.tf32.f32 "
        "{%0,%1,%2,%3}, {%4,%5,%6,%7}, {%8,%9}, {%0,%1,%2,%3};"
        : "+f"(c.x), "+f"(c.y), "+f"(c.z), "+f"(c.w)
        : "r"(a[0]), "r"(a[1]), "r"(a[2]), "r"(a[3]), "r"(b0), "r"(b1));
}

// ---------------- zero accumulators ------------------------------------------
__global__ void zero_kernel() {
    int i = blockIdx.x * blockDim.x + threadIdx.x;
    if (i < NN) g_cnt[i] = 0u;
    if (i < HD) { g_sums[i] = 0.f; g_sumsq[i] = 0.f; }
}

// ---------------- GEMM h = x@W via tf32 mma + el/er epilogue -----------------
// Block tile 128x128, K-tile 32. 8 warps as 2x4; warp tile 64x32 (4x4 mmas).
// Warp-column wc owns exactly head wc (cols [wc*32, wc*32+32)).
#define SA 36    // As row stride (uint32): banks (4*gid+tig) distinct
#define SB 136   // Bs row stride (uint32): banks (8*tig+gid) distinct
__global__ void __launch_bounds__(256) gemm_kernel(
    const float* __restrict__ x, const float* __restrict__ W,
    const float* __restrict__ attn_l, const float* __restrict__ attn_r)
{
    __shared__ unsigned As[128 * SA];
    __shared__ unsigned Bs[32 * SB];
    const int tid  = threadIdx.x;
    const int warp = tid >> 5, lane = tid & 31;
    const int wr = warp >> 2, wc = warp & 3;
    const int gid = lane >> 2, tig = lane & 3;
    const int row0 = blockIdx.x * 128;

    float4 c[4][4];
#pragma unroll
    for (int mt = 0; mt < 4; mt++)
#pragma unroll
        for (int nt = 0; nt < 4; nt++) c[mt][nt] = make_float4(0.f, 0.f, 0.f, 0.f);

    const int ldr = tid >> 3;          // 0..31
    const int ldc = (tid & 7) * 4;     // A col offset {0,4,..,28}

    for (int k0 = 0; k0 < IN_DIM; k0 += 32) {
        // ---- load A tile (128x32) as tf32 ----
#pragma unroll
        for (int rr = 0; rr < 4; rr++) {
            int lrow = ldr + rr * 32;
            int gr = row0 + lrow;
            float4 v = make_float4(0.f, 0.f, 0.f, 0.f);
            if (gr < NN) v = *(const float4*)&x[gr * IN_DIM + k0 + ldc];
            uint4 u = make_uint4(f2tf32(v.x), f2tf32(v.y), f2tf32(v.z), f2tf32(v.w));
            *(uint4*)&As[lrow * SA + ldc] = u;
        }
        // ---- load B tile (32x128) as tf32 ----
#pragma unroll
        for (int j = 0; j < 4; j++) {
            int cc = ((tid & 7) + j * 8) * 4;
            float4 v = *(const float4*)&W[(k0 + ldr) * HD + cc];
            uint4 u = make_uint4(f2tf32(v.x), f2tf32(v.y), f2tf32(v.z), f2tf32(v.w));
            *(uint4*)&Bs[ldr * SB + cc] = u;
        }
        __syncthreads();

#pragma unroll
        for (int kk = 0; kk < 4; kk++) {
            unsigned a[4][4], b[4][2];
            const int kb = kk * 8 + tig;
#pragma unroll
            for (int mt = 0; mt < 4; mt++) {
                int row = wr * 64 + mt * 16 + gid;
                a[mt][0] = As[row * SA + kb];
                a[mt][1] = As[(row + 8) * SA + kb];
                a[mt][2] = As[row * SA + kb + 4];
                a[mt][3] = As[(row + 8) * SA + kb + 4];
            }
#pragma unroll
            for (int nt = 0; nt < 4; nt++) {
                int col = wc * 32 + nt * 8 + gid;
                b[nt][0] = Bs[kb * SB + col];
                b[nt][1] = Bs[(kb + 4) * SB + col];
            }
#pragma unroll
            for (int mt = 0; mt < 4; mt++)
#pragma unroll
                for (int nt = 0; nt < 4; nt++)
                    mma_tf32(c[mt][nt], a[mt], b[nt][0], b[nt][1]);
        }
        __syncthreads();
    }

    // ---- epilogue: store h, reduce el/er (warp-col wc == head) ----
    const int head = wc;
    float al[4][2], arr[4][2];
#pragma unroll
    for (int nt = 0; nt < 4; nt++) {
        int col = wc * 32 + nt * 8 + 2 * tig;
        al[nt][0] = attn_l[col];     al[nt][1] = attn_l[col + 1];
        arr[nt][0] = attn_r[col];    arr[nt][1] = attn_r[col + 1];
    }

#pragma unroll
    for (int mt = 0; mt < 4; mt++) {
        int r0 = row0 + wr * 64 + mt * 16 + gid;     // and r0+8
        float pl0 = 0.f, pr0 = 0.f, pl1 = 0.f, pr1 = 0.f;
#pragma unroll
        for (int nt = 0; nt < 4; nt++) {
            float4 v = c[mt][nt];
            pl0 = fmaf(v.x, al[nt][0], fmaf(v.y, al[nt][1], pl0));
            pr0 = fmaf(v.x, arr[nt][0], fmaf(v.y, arr[nt][1], pr0));
            pl1 = fmaf(v.z, al[nt][0], fmaf(v.w, al[nt][1], pl1));
            pr1 = fmaf(v.z, arr[nt][0], fmaf(v.w, arr[nt][1], pr1));
        }
#pragma unroll
        for (int o = 1; o <= 2; o <<= 1) {
            pl0 += __shfl_xor_sync(0xffffffffu, pl0, o);
            pr0 += __shfl_xor_sync(0xffffffffu, pr0, o);
            pl1 += __shfl_xor_sync(0xffffffffu, pl1, o);
            pr1 += __shfl_xor_sync(0xffffffffu, pr1, o);
        }
        if (tig == 0) {
            if (r0 < NN)     { g_el[r0 * 4 + head] = pl0;       g_er[r0 * 4 + head] = pr0; }
            if (r0 + 8 < NN) { g_el[(r0 + 8) * 4 + head] = pl1; g_er[(r0 + 8) * 4 + head] = pr1; }
        }
#pragma unroll
        for (int nt = 0; nt < 4; nt++) {
            int col = wc * 32 + nt * 8 + 2 * tig;
            float4 v = c[mt][nt];
            if (r0 < NN)     *(float2*)&g_h[r0 * HD + col]       = make_float2(v.x, v.y);
            if (r0 + 8 < NN) *(float2*)&g_h[(r0 + 8) * HD + col] = make_float2(v.z, v.w);
        }
    }
}

// ---------------- CSR build: histogram ---------------------------------------
__global__ void hist_kernel(const int* __restrict__ dst) {
    int e = blockIdx.x * blockDim.x + threadIdx.x;
    if (e < EE) atomicAdd(&g_cnt[dst[e]], 1u);
}

// ---------------- CSR build: two-level scan ----------------------------------
__global__ void scan_block_kernel() {
    __shared__ unsigned sh[256];
    int t = threadIdx.x;
    int idx = blockIdx.x * 256 + t;
    unsigned v = (idx < NN) ? g_cnt[idx] : 0u;
    sh[t] = v;
    __syncthreads();
#pragma unroll
    for (int off = 1; off < 256; off <<= 1) {
        unsigned p = (t >= off) ? sh[t - off] : 0u;
        __syncthreads();
        sh[t] += p;
        __syncthreads();
    }
    if (idx < NN) g_off[idx] = sh[t] - v;            // local exclusive
    if (t == 255) g_bsum[blockIdx.x] = sh[255];
}

__global__ void scan_top_kernel() {
    __shared__ unsigned sh[256];
    int t = threadIdx.x;
    unsigned v = (t < NB) ? g_bsum[t] : 0u;
    sh[t] = v;
    __syncthreads();
#pragma unroll
    for (int off = 1; off < 256; off <<= 1) {
        unsigned p = (t >= off) ? sh[t - off] : 0u;
        __syncthreads();
        sh[t] += p;
        __syncthreads();
    }
    if (t < NB) g_bpre[t] = sh[t] - v;               // exclusive
}

__global__ void scan_add_kernel() {
    int idx = blockIdx.x * 256 + threadIdx.x;
    if (idx < NN) {
        unsigned o = g_off[idx] + g_bpre[blockIdx.x];
        g_off[idx] = o;
        g_cur[idx] = o;
    }
    if (idx == 0) g_off[NN] = EE;
}

// ---------------- CSR build: scatter edge sources ----------------------------
__global__ void scatter_kernel(const int* __restrict__ src,
                               const int* __restrict__ dst) {
    int e = blockIdx.x * blockDim.x + threadIdx.x;
    if (e >= EE) return;
    int d = dst[e];
    unsigned pos = atomicAdd(&g_cur[d], 1u);
    g_esrc[pos] = src[e];
}

// ---------------- fused softmax + aggregation: one warp per dst node ---------
__global__ void __launch_bounds__(256) agg_kernel() {
    int gwarp = (blockIdx.x * 256 + threadIdx.x) >> 5;
    int l = threadIdx.x & 31;
    if (gwarp >= NN) return;
    const int d = gwarp;
    const int beg = (int)g_off[d], end = (int)g_off[d + 1];

    const float4 er4 = ((const float4*)g_er)[d];
    const int hh = l >> 3;                 // 8 lanes per head
    const float erc = sel4(er4, hh);

    float4 acc = make_float4(0.f, 0.f, 0.f, 0.f);
    float sumex = 0.f;

    int sn = (beg < end) ? __ldg(&g_esrc[beg]) : 0;
    for (int i = beg; i < end; i++) {
        int s = sn;
        if (i + 1 < end) sn = __ldg(&g_esrc[i + 1]);
        float4 el4 = ((const float4*)g_el)[s];
        float e = sel4(el4, hh) + erc;
        e = e > 0.f ? e : NEG_SLOPE * e;
        float ex = __expf(e);
        sumex += ex;
        float4 hv = ((const float4*)g_h)[s * 32 + l];
        acc.x = fmaf(ex, hv.x, acc.x);
        acc.y = fmaf(ex, hv.y, acc.y);
        acc.z = fmaf(ex, hv.z, acc.z);
        acc.w = fmaf(ex, hv.w, acc.w);
    }
    float inv = (sumex > 0.f) ? 1.f / sumex : 0.f;
    float4 o;
    o.x = acc.x * inv; o.y = acc.y * inv; o.z = acc.z * inv; o.w = acc.w * inv;
    ((float4*)g_rst)[d * 32 + l] = o;
}

// ---------------- BN stats ---------------------------------------------------
__global__ void bn_stats_kernel() {
    int c = threadIdx.x;                 // 128 threads = channels
    float s = 0.f, s2 = 0.f;
    for (int r = blockIdx.x; r < NN; r += gridDim.x) {
        float v = g_rst[r * HD + c];
        s += v; s2 += v * v;
    }
    atomicAdd(&g_sums[c], s);
    atomicAdd(&g_sumsq[c], s2);
}

// ---------------- BN normalize + ReLU ---------------------------------------
__global__ void bn_apply_kernel(const float* __restrict__ gamma,
                                const float* __restrict__ beta,
                                float* __restrict__ out)
{
    int i = blockIdx.x * blockDim.x + threadIdx.x;   // NN*HD threads
    int c = i & (HD - 1);
    const float inv_n = 1.f / (float)NN;
    float mean = g_sums[c] * inv_n;
    float var  = g_sumsq[c] * inv_n - mean * mean;
    float y = gamma[c] * (g_rst[i] - mean) * rsqrtf(var + BN_EPS) + beta[c];
    out[i] = y > 0.f ? y : 0.f;
}

// ---------------- launch -----------------------------------------------------
extern "C" void kernel_launch(void* const* d_in, const int* in_sizes, int n_in,
                              void* d_out, int out_size)
{
    const float* x      = (const float*)d_in[0];
    const int*   src    = (const int*)d_in[1];
    const int*   dst    = (const int*)d_in[2];
    const float* W      = (const float*)d_in[3];
    const float* attn_l = (const float*)d_in[4];
    const float* attn_r = (const float*)d_in[5];
    // d_in[6] = bias: constant per-channel shift, cancels inside batch-norm
    const float* gamma  = (const float*)d_in[7];
    const float* beta   = (const float*)d_in[8];
    float* out = (float*)d_out;

    zero_kernel<<<(NN + 255) / 256, 256>>>();
    gemm_kernel<<<(NN + 127) / 128, 256>>>(x, W, attn_l, attn_r);
    hist_kernel<<<(EE + 255) / 256, 256>>>(dst);
    scan_block_kernel<<<NB, 256>>>();
    scan_top_kernel<<<1, 256>>>();
    scan_add_kernel<<<NB, 256>>>();
    scatter_kernel<<<(EE + 255) / 256, 256>>>(src, dst);
    agg_kernel<<<(NN * 32 + 255) / 256, 256>>>();
    bn_stats_kernel<<<512, 128>>>();
    bn_apply_kernel<<<(NN * HD) / 256, 256>>>(gamma, beta, out);
}

// round 5
// speedup vs baseline: 2.0299x; 1.1037x over previous
#include <cuda_runtime.h>
#include <cuda_bf16.h>

#define NN 50000
#define EE 800000
#define HD 128            // H*D
#define IN_DIM 256
#define NEG_SLOPE 0.2f
#define BN_EPS 1e-5f
#define NB 196            // ceil(NN/256) scan blocks

// ---------------- scratch (device globals; no allocations allowed) -----------
__device__ float    g_h[NN * HD];       // projected features [N,128]
__device__ float    g_el[NN * 4];       // attn-left  per node per head
__device__ float    g_er[NN * 4];       // attn-right per node per head
__device__ unsigned g_cnt[NN];          // in-degree histogram
__device__ unsigned g_off[NN + 1];      // CSR offsets (by dst)
__device__ unsigned g_cur[NN];          // scatter cursors
__device__ unsigned g_bsum[NB];         // per-block count sums
__device__ unsigned g_bpre[NB];         // exclusive prefix of block sums
__device__ int      g_esrc[EE];         // src node id per CSR slot
__device__ float    g_rst[NN * HD];     // aggregated messages
__device__ float    g_sums[HD];
__device__ float    g_sumsq[HD];

__device__ __forceinline__ float sel4(float4 v, int i) {
    float r = v.x;
    if (i == 1) r = v.y; else if (i == 2) r = v.z; else if (i == 3) r = v.w;
    return r;
}

__device__ __forceinline__ unsigned f2tf32(float f) {
    unsigned u;
    asm("cvt.rna.tf32.f32 %0, %1;" : "=r"(u) : "f"(f));
    return u;
}

__device__ __forceinline__ void mma_tf32(float4& c, const unsigned a[4],
                                         unsigned b0, unsigned b1) {
    asm volatile(
        "mma.sync.aligned.m16n8k8.row.col.f32.tf32.tf32.f32 "
        "{%0,%1,%2,%3}, {%4,%5,%6,%7}, {%8,%9}, {%0,%1,%2,%3};"
        : "+f"(c.x), "+f"(c.y), "+f"(c.z), "+f"(c.w)
        : "r"(a[0]), "r"(a[1]), "r"(a[2]), "r"(a[3]), "r"(b0), "r"(b1));
}

// ---------------- zero accumulators ------------------------------------------
__global__ void zero_kernel() {
    int i = blockIdx.x * blockDim.x + threadIdx.x;
    if (i < NN) g_cnt[i] = 0u;
    if (i < HD) { g_sums[i] = 0.f; g_sumsq[i] = 0.f; }
}

// ---------------- GEMM h = x@W via tf32 mma + el/er epilogue -----------------
// Block tile 128x128, K-tile 32. 8 warps as 2x4; warp tile 64x32 (4x4 mmas).
// Warp-column wc owns exactly head wc (cols [wc*32, wc*32+32)).
#define SA 36    // As row stride (uint32): banks (4*gid+tig) distinct
#define SB 136   // Bs row stride (uint32): banks (8*tig+gid) distinct
__global__ void __launch_bounds__(256) gemm_kernel(
    const float* __restrict__ x, const float* __restrict__ W,
    const float* __restrict__ attn_l, const float* __restrict__ attn_r)
{
    __shared__ unsigned As[128 * SA];
    __shared__ unsigned Bs[32 * SB];
    const int tid  = threadIdx.x;
    const int warp = tid >> 5, lane = tid & 31;
    const int wr = warp >> 2, wc = warp & 3;
    const int gid = lane >> 2, tig = lane & 3;
    const int row0 = blockIdx.x * 128;

    float4 c[4][4];
#pragma unroll
    for (int mt = 0; mt < 4; mt++)
#pragma unroll
        for (int nt = 0; nt < 4; nt++) c[mt][nt] = make_float4(0.f, 0.f, 0.f, 0.f);

    const int ldr = tid >> 3;          // 0..31
    const int ldc = (tid & 7) * 4;     // A col offset {0,4,..,28}

    for (int k0 = 0; k0 < IN_DIM; k0 += 32) {
        // ---- load A tile (128x32) as tf32 ----
#pragma unroll
        for (int rr = 0; rr < 4; rr++) {
            int lrow = ldr + rr * 32;
            int gr = row0 + lrow;
            float4 v = make_float4(0.f, 0.f, 0.f, 0.f);
            if (gr < NN) v = *(const float4*)&x[gr * IN_DIM + k0 + ldc];
            uint4 u = make_uint4(f2tf32(v.x), f2tf32(v.y), f2tf32(v.z), f2tf32(v.w));
            *(uint4*)&As[lrow * SA + ldc] = u;
        }
        // ---- load B tile (32x128) as tf32 ----
#pragma unroll
        for (int j = 0; j < 4; j++) {
            int cc = ((tid & 7) + j * 8) * 4;
            float4 v = *(const float4*)&W[(k0 + ldr) * HD + cc];
            uint4 u = make_uint4(f2tf32(v.x), f2tf32(v.y), f2tf32(v.z), f2tf32(v.w));
            *(uint4*)&Bs[ldr * SB + cc] = u;
        }
        __syncthreads();

#pragma unroll
        for (int kk = 0; kk < 4; kk++) {
            unsigned a[4][4], b[4][2];
            const int kb = kk * 8 + tig;
#pragma unroll
            for (int mt = 0; mt < 4; mt++) {
                int row = wr * 64 + mt * 16 + gid;
                a[mt][0] = As[row * SA + kb];
                a[mt][1] = As[(row + 8) * SA + kb];
                a[mt][2] = As[row * SA + kb + 4];
                a[mt][3] = As[(row + 8) * SA + kb + 4];
            }
#pragma unroll
            for (int nt = 0; nt < 4; nt++) {
                int col = wc * 32 + nt * 8 + gid;
                b[nt][0] = Bs[kb * SB + col];
                b[nt][1] = Bs[(kb + 4) * SB + col];
            }
#pragma unroll
            for (int mt = 0; mt < 4; mt++)
#pragma unroll
                for (int nt = 0; nt < 4; nt++)
                    mma_tf32(c[mt][nt], a[mt], b[nt][0], b[nt][1]);
        }
        __syncthreads();
    }

    // ---- epilogue: store h, reduce el/er (warp-col wc == head) ----
    const int head = wc;
    float al[4][2], arr[4][2];
#pragma unroll
    for (int nt = 0; nt < 4; nt++) {
        int col = wc * 32 + nt * 8 + 2 * tig;
        al[nt][0] = attn_l[col];     al[nt][1] = attn_l[col + 1];
        arr[nt][0] = attn_r[col];    arr[nt][1] = attn_r[col + 1];
    }

#pragma unroll
    for (int mt = 0; mt < 4; mt++) {
        int r0 = row0 + wr * 64 + mt * 16 + gid;     // and r0+8
        float pl0 = 0.f, pr0 = 0.f, pl1 = 0.f, pr1 = 0.f;
#pragma unroll
        for (int nt = 0; nt < 4; nt++) {
            float4 v = c[mt][nt];
            pl0 = fmaf(v.x, al[nt][0], fmaf(v.y, al[nt][1], pl0));
            pr0 = fmaf(v.x, arr[nt][0], fmaf(v.y, arr[nt][1], pr0));
            pl1 = fmaf(v.z, al[nt][0], fmaf(v.w, al[nt][1], pl1));
            pr1 = fmaf(v.z, arr[nt][0], fmaf(v.w, arr[nt][1], pr1));
        }
#pragma unroll
        for (int o = 1; o <= 2; o <<= 1) {
            pl0 += __shfl_xor_sync(0xffffffffu, pl0, o);
            pr0 += __shfl_xor_sync(0xffffffffu, pr0, o);
            pl1 += __shfl_xor_sync(0xffffffffu, pl1, o);
            pr1 += __shfl_xor_sync(0xffffffffu, pr1, o);
        }
        if (tig == 0) {
            if (r0 < NN)     { g_el[r0 * 4 + head] = pl0;       g_er[r0 * 4 + head] = pr0; }
            if (r0 + 8 < NN) { g_el[(r0 + 8) * 4 + head] = pl1; g_er[(r0 + 8) * 4 + head] = pr1; }
        }
#pragma unroll
        for (int nt = 0; nt < 4; nt++) {
            int col = wc * 32 + nt * 8 + 2 * tig;
            float4 v = c[mt][nt];
            if (r0 < NN)     *(float2*)&g_h[r0 * HD + col]       = make_float2(v.x, v.y);
            if (r0 + 8 < NN) *(float2*)&g_h[(r0 + 8) * HD + col] = make_float2(v.z, v.w);
        }
    }
}

// ---------------- CSR build: histogram ---------------------------------------
__global__ void hist_kernel(const int* __restrict__ dst) {
    int e = blockIdx.x * blockDim.x + threadIdx.x;
    if (e < EE) atomicAdd(&g_cnt[dst[e]], 1u);
}

// ---------------- CSR build: two-level scan ----------------------------------
__global__ void scan_block_kernel() {
    __shared__ unsigned sh[256];
    int t = threadIdx.x;
    int idx = blockIdx.x * 256 + t;
    unsigned v = (idx < NN) ? g_cnt[idx] : 0u;
    sh[t] = v;
    __syncthreads();
#pragma unroll
    for (int off = 1; off < 256; off <<= 1) {
        unsigned p = (t >= off) ? sh[t - off] : 0u;
        __syncthreads();
        sh[t] += p;
        __syncthreads();
    }
    if (idx < NN) g_off[idx] = sh[t] - v;            // local exclusive
    if (t == 255) g_bsum[blockIdx.x] = sh[255];
}

__global__ void scan_top_kernel() {
    __shared__ unsigned sh[256];
    int t = threadIdx.x;
    unsigned v = (t < NB) ? g_bsum[t] : 0u;
    sh[t] = v;
    __syncthreads();
#pragma unroll
    for (int off = 1; off < 256; off <<= 1) {
        unsigned p = (t >= off) ? sh[t - off] : 0u;
        __syncthreads();
        sh[t] += p;
        __syncthreads();
    }
    if (t < NB) g_bpre[t] = sh[t] - v;               // exclusive
}

__global__ void scan_add_kernel() {
    int idx = blockIdx.x * 256 + threadIdx.x;
    if (idx < NN) {
        unsigned o = g_off[idx] + g_bpre[blockIdx.x];
        g_off[idx] = o;
        g_cur[idx] = o;
    }
    if (idx == 0) g_off[NN] = EE;
}

// ---------------- CSR build: scatter edge sources ----------------------------
__global__ void scatter_kernel(const int* __restrict__ src,
                               const int* __restrict__ dst) {
    int e = blockIdx.x * blockDim.x + threadIdx.x;
    if (e >= EE) return;
    int d = dst[e];
    unsigned pos = atomicAdd(&g_cur[d], 1u);
    g_esrc[pos] = src[e];
}

// ---------------- fused softmax + aggregation: one warp per dst node ---------
// 2-edge software pipeline: 4+ independent L2 loads in flight per iteration.
__global__ void __launch_bounds__(256) agg_kernel() {
    int gwarp = (blockIdx.x * 256 + threadIdx.x) >> 5;
    int l = threadIdx.x & 31;
    if (gwarp >= NN) return;
    const int d = gwarp;
    const int beg = (int)g_off[d], end = (int)g_off[d + 1];

    const float4 er4 = ((const float4*)g_er)[d];
    const int hh = l >> 3;                 // 8 lanes per head
    const float erc = sel4(er4, hh);

    float4 acc = make_float4(0.f, 0.f, 0.f, 0.f);
    float sumex = 0.f;

    int i = beg;
    for (; i + 1 < end; i += 2) {
        int s0 = __ldg(&g_esrc[i]);
        int s1 = __ldg(&g_esrc[i + 1]);
        float4 el0 = ((const float4*)g_el)[s0];
        float4 el1 = ((const float4*)g_el)[s1];
        float4 h0 = ((const float4*)g_h)[s0 * 32 + l];
        float4 h1 = ((const float4*)g_h)[s1 * 32 + l];

        float e0 = sel4(el0, hh) + erc;
        e0 = e0 > 0.f ? e0 : NEG_SLOPE * e0;
        float ex0 = __expf(e0);
        float e1 = sel4(el1, hh) + erc;
        e1 = e1 > 0.f ? e1 : NEG_SLOPE * e1;
        float ex1 = __expf(e1);

        sumex += ex0 + ex1;
        acc.x = fmaf(ex0, h0.x, fmaf(ex1, h1.x, acc.x));
        acc.y = fmaf(ex0, h0.y, fmaf(ex1, h1.y, acc.y));
        acc.z = fmaf(ex0, h0.z, fmaf(ex1, h1.z, acc.z));
        acc.w = fmaf(ex0, h0.w, fmaf(ex1, h1.w, acc.w));
    }
    if (i < end) {
        int s = __ldg(&g_esrc[i]);
        float4 el4 = ((const float4*)g_el)[s];
        float4 hv = ((const float4*)g_h)[s * 32 + l];
        float e = sel4(el4, hh) + erc;
        e = e > 0.f ? e : NEG_SLOPE * e;
        float ex = __expf(e);
        sumex += ex;
        acc.x = fmaf(ex, hv.x, acc.x);
        acc.y = fmaf(ex, hv.y, acc.y);
        acc.z = fmaf(ex, hv.z, acc.z);
        acc.w = fmaf(ex, hv.w, acc.w);
    }
    float inv = (sumex > 0.f) ? 1.f / sumex : 0.f;
    float4 o;
    o.x = acc.x * inv; o.y = acc.y * inv; o.z = acc.z * inv; o.w = acc.w * inv;
    ((float4*)g_rst)[d * 32 + l] = o;
}

// ---------------- BN stats ---------------------------------------------------
__global__ void bn_stats_kernel() {
    int c = threadIdx.x;                 // 128 threads = channels
    float s = 0.f, s2 = 0.f;
    for (int r = blockIdx.x; r < NN; r += gridDim.x) {
        float v = g_rst[r * HD + c];
        s += v; s2 += v * v;
    }
    atomicAdd(&g_sums[c], s);
    atomicAdd(&g_sumsq[c], s2);
}

// ---------------- BN normalize + ReLU (vectorized) ---------------------------
__global__ void bn_apply_kernel(const float* __restrict__ gamma,
                                const float* __restrict__ beta,
                                float* __restrict__ out)
{
    int i = blockIdx.x * blockDim.x + threadIdx.x;   // NN*HD/4 threads
    int c0 = (i * 4) & (HD - 1);
    const float inv_n = 1.f / (float)NN;
    float4 v = ((const float4*)g_rst)[i];
    float4 o;
#pragma unroll
    for (int j = 0; j < 4; j++) {
        int c = c0 + j;
        float mean = g_sums[c] * inv_n;
        float var  = g_sumsq[c] * inv_n - mean * mean;
        float vv = (j == 0) ? v.x : (j == 1) ? v.y : (j == 2) ? v.z : v.w;
        float y = gamma[c] * (vv - mean) * rsqrtf(var + BN_EPS) + beta[c];
        y = y > 0.f ? y : 0.f;
        if (j == 0) o.x = y; else if (j == 1) o.y = y;
        else if (j == 2) o.z = y; else o.w = y;
    }
    ((float4*)out)[i] = o;
}

// ---------------- launch -----------------------------------------------------
// NOTE: launch order chosen so gemm_kernel is the 4th launch (ncu profiles #4).
extern "C" void kernel_launch(void* const* d_in, const int* in_sizes, int n_in,
                              void* d_out, int out_size)
{
    const float* x      = (const float*)d_in[0];
    const int*   src    = (const int*)d_in[1];
    const int*   dst    = (const int*)d_in[2];
    const float* W      = (const float*)d_in[3];
    const float* attn_l = (const float*)d_in[4];
    const float* attn_r = (const float*)d_in[5];
    // d_in[6] = bias: constant per-channel shift, cancels inside batch-norm
    const float* gamma  = (const float*)d_in[7];
    const float* beta   = (const float*)d_in[8];
    float* out = (float*)d_out;

    zero_kernel<<<(NN + 255) / 256, 256>>>();
    hist_kernel<<<(EE + 255) / 256, 256>>>(dst);
    scan_block_kernel<<<NB, 256>>>();
    gemm_kernel<<<(NN + 127) / 128, 256>>>(x, W, attn_l, attn_r);   // profiled
    scan_top_kernel<<<1, 256>>>();
    scan_add_kernel<<<NB, 256>>>();
    scatter_kernel<<<(EE + 255) / 256, 256>>>(src, dst);
    agg_kernel<<<(NN * 32 + 255) / 256, 256>>>();
    bn_stats_kernel<<<512, 128>>>();
    bn_apply_kernel<<<(NN * HD / 4 + 255) / 256, 256>>>(gamma, beta, out);
}

// round 6
// speedup vs baseline: 2.1109x; 1.0399x over previous
#include <cuda_runtime.h>
#include <cuda_bf16.h>
#include <cuda_fp16.h>

#define NN 50000
#define EE 800000
#define HD 128            // H*D
#define IN_DIM 256
#define NEG_SLOPE 0.2f
#define BN_EPS 1e-5f
#define NB 196            // ceil(NN/256) scan blocks

// ---------------- scratch (device globals; no allocations allowed) -----------
__device__ __half   g_hh[NN * HD];      // projected features fp16 [N,128]
__device__ float    g_el[NN * 4];       // attn-left  per node per head (fp32)
__device__ float    g_er[NN * 4];       // attn-right per node per head (fp32)
__device__ unsigned g_cnt[NN];          // in-degree histogram
__device__ unsigned g_off[NN + 1];      // CSR offsets (by dst)
__device__ unsigned g_cur[NN];          // scatter cursors
__device__ unsigned g_bsum[NB];         // per-block count sums
__device__ unsigned g_bpre[NB];         // exclusive prefix of block sums
__device__ int      g_esrc[EE];         // src node id per CSR slot
__device__ float    g_rst[NN * HD];     // aggregated messages (fp32)
__device__ float    g_sums[HD];
__device__ float    g_sumsq[HD];

__device__ __forceinline__ float sel4(float4 v, int i) {
    float r = v.x;
    if (i == 1) r = v.y; else if (i == 2) r = v.z; else if (i == 3) r = v.w;
    return r;
}

__device__ __forceinline__ unsigned f2tf32(float f) {
    unsigned u;
    asm("cvt.rna.tf32.f32 %0, %1;" : "=r"(u) : "f"(f));
    return u;
}

__device__ __forceinline__ void mma_tf32(float4& c, const unsigned a[4],
                                         unsigned b0, unsigned b1) {
    asm volatile(
        "mma.sync.aligned.m16n8k8.row.col.f32.tf32.tf32.f32 "
        "{%0,%1,%2,%3}, {%4,%5,%6,%7}, {%8,%9}, {%0,%1,%2,%3};"
        : "+f"(c.x), "+f"(c.y), "+f"(c.z), "+f"(c.w)
        : "r"(a[0]), "r"(a[1]), "r"(a[2]), "r"(a[3]), "r"(b0), "r"(b1));
}

// ---------------- zero accumulators ------------------------------------------
__global__ void zero_kernel() {
    int i = blockIdx.x * blockDim.x + threadIdx.x;
    if (i < NN) g_cnt[i] = 0u;
    if (i < HD) { g_sums[i] = 0.f; g_sumsq[i] = 0.f; }
}

// ---------------- GEMM h = x@W via tf32 mma, software-pipelined --------------
// Block tile 128x128, K-tile 16. 8 warps 2x4; warp tile 64x32 (4x4 mmas).
// Register-staged double buffering: LDG for tile i+1 issued before compute of
// tile i, hiding global latency under the mma block.
#define SA2 20   // As row stride (uint32): banks (20*gid+tig) distinct mod 32
#define SB2 136  // Bs row stride (uint32): banks (8*tig+gid) distinct mod 32
__global__ void __launch_bounds__(256, 2) gemm_kernel(
    const float* __restrict__ x, const float* __restrict__ W,
    const float* __restrict__ attn_l, const float* __restrict__ attn_r)
{
    __shared__ unsigned As[128 * SA2];
    __shared__ unsigned Bs[16 * SB2];
    const int tid  = threadIdx.x;
    const int warp = tid >> 5, lane = tid & 31;
    const int wr = warp >> 2, wc = warp & 3;
    const int gid = lane >> 2, tig = lane & 3;
    const int row0 = blockIdx.x * 128;

    // staging maps
    const int arow = tid >> 1, acol = (tid & 1) * 8;     // A: 128x16
    const int brow = tid >> 4, bcol = (tid & 15) * 8;    // B: 16x128
    const int agr = row0 + arow;
    const float* aptr = x + (long)agr * IN_DIM + acol;
    const float* bptr = W + brow * HD + bcol;

    float4 ar0, ar1, br0, br1;
    ar0 = make_float4(0.f, 0.f, 0.f, 0.f); ar1 = ar0;
    if (agr < NN) {
        ar0 = *(const float4*)(aptr + 0);
        ar1 = *(const float4*)(aptr + 4);
    }
    br0 = *(const float4*)(bptr + 0);
    br1 = *(const float4*)(bptr + 4);

    float4 c[4][4];
#pragma unroll
    for (int mt = 0; mt < 4; mt++)
#pragma unroll
        for (int nt = 0; nt < 4; nt++) c[mt][nt] = make_float4(0.f, 0.f, 0.f, 0.f);

    for (int k0 = 0; k0 < IN_DIM; k0 += 16) {
        // ---- store staged tile (cvt to tf32) ----
        *(uint4*)&As[arow * SA2 + acol] =
            make_uint4(f2tf32(ar0.x), f2tf32(ar0.y), f2tf32(ar0.z), f2tf32(ar0.w));
        *(uint4*)&As[arow * SA2 + acol + 4] =
            make_uint4(f2tf32(ar1.x), f2tf32(ar1.y), f2tf32(ar1.z), f2tf32(ar1.w));
        *(uint4*)&Bs[brow * SB2 + bcol] =
            make_uint4(f2tf32(br0.x), f2tf32(br0.y), f2tf32(br0.z), f2tf32(br0.w));
        *(uint4*)&Bs[brow * SB2 + bcol + 4] =
            make_uint4(f2tf32(br1.x), f2tf32(br1.y), f2tf32(br1.z), f2tf32(br1.w));
        __syncthreads();

        // ---- prefetch next tile (latency overlaps compute below) ----
        if (k0 + 16 < IN_DIM) {
            if (agr < NN) {
                ar0 = *(const float4*)(aptr + k0 + 16);
                ar1 = *(const float4*)(aptr + k0 + 20);
            }
            br0 = *(const float4*)(bptr + (k0 + 16) * HD);
            br1 = *(const float4*)(bptr + (k0 + 16) * HD + 4);
        }

        // ---- compute: 2 kk steps of 8 ----
#pragma unroll
        for (int kk = 0; kk < 2; kk++) {
            unsigned a[4][4], b[4][2];
            const int kb = kk * 8 + tig;
#pragma unroll
            for (int mt = 0; mt < 4; mt++) {
                int row = wr * 64 + mt * 16 + gid;
                a[mt][0] = As[row * SA2 + kb];
                a[mt][1] = As[(row + 8) * SA2 + kb];
                a[mt][2] = As[row * SA2 + kb + 4];
                a[mt][3] = As[(row + 8) * SA2 + kb + 4];
            }
#pragma unroll
            for (int nt = 0; nt < 4; nt++) {
                int col = wc * 32 + nt * 8 + gid;
                b[nt][0] = Bs[kb * SB2 + col];
                b[nt][1] = Bs[(kb + 4) * SB2 + col];
            }
#pragma unroll
            for (int mt = 0; mt < 4; mt++)
#pragma unroll
                for (int nt = 0; nt < 4; nt++)
                    mma_tf32(c[mt][nt], a[mt], b[nt][0], b[nt][1]);
        }
        __syncthreads();
    }

    // ---- epilogue: store h (fp16), reduce el/er fp32 (warp-col wc == head) --
    const int head = wc;
    float al[4][2], arr[4][2];
#pragma unroll
    for (int nt = 0; nt < 4; nt++) {
        int col = wc * 32 + nt * 8 + 2 * tig;
        al[nt][0] = attn_l[col];     al[nt][1] = attn_l[col + 1];
        arr[nt][0] = attn_r[col];    arr[nt][1] = attn_r[col + 1];
    }

#pragma unroll
    for (int mt = 0; mt < 4; mt++) {
        int r0 = row0 + wr * 64 + mt * 16 + gid;     // and r0+8
        float pl0 = 0.f, pr0 = 0.f, pl1 = 0.f, pr1 = 0.f;
#pragma unroll
        for (int nt = 0; nt < 4; nt++) {
            float4 v = c[mt][nt];
            pl0 = fmaf(v.x, al[nt][0], fmaf(v.y, al[nt][1], pl0));
            pr0 = fmaf(v.x, arr[nt][0], fmaf(v.y, arr[nt][1], pr0));
            pl1 = fmaf(v.z, al[nt][0], fmaf(v.w, al[nt][1], pl1));
            pr1 = fmaf(v.z, arr[nt][0], fmaf(v.w, arr[nt][1], pr1));
        }
#pragma unroll
        for (int o = 1; o <= 2; o <<= 1) {
            pl0 += __shfl_xor_sync(0xffffffffu, pl0, o);
            pr0 += __shfl_xor_sync(0xffffffffu, pr0, o);
            pl1 += __shfl_xor_sync(0xffffffffu, pl1, o);
            pr1 += __shfl_xor_sync(0xffffffffu, pr1, o);
        }
        if (tig == 0) {
            if (r0 < NN)     { g_el[r0 * 4 + head] = pl0;       g_er[r0 * 4 + head] = pr0; }
            if (r0 + 8 < NN) { g_el[(r0 + 8) * 4 + head] = pl1; g_er[(r0 + 8) * 4 + head] = pr1; }
        }
#pragma unroll
        for (int nt = 0; nt < 4; nt++) {
            int col = wc * 32 + nt * 8 + 2 * tig;
            float4 v = c[mt][nt];
            if (r0 < NN)
                *(__half2*)&g_hh[r0 * HD + col]       = __floats2half2_rn(v.x, v.y);
            if (r0 + 8 < NN)
                *(__half2*)&g_hh[(r0 + 8) * HD + col] = __floats2half2_rn(v.z, v.w);
        }
    }
}

// ---------------- CSR build: histogram ---------------------------------------
__global__ void hist_kernel(const int* __restrict__ dst) {
    int e = blockIdx.x * blockDim.x + threadIdx.x;
    if (e < EE) atomicAdd(&g_cnt[dst[e]], 1u);
}

// ---------------- CSR build: two-level scan ----------------------------------
__global__ void scan_block_kernel() {
    __shared__ unsigned sh[256];
    int t = threadIdx.x;
    int idx = blockIdx.x * 256 + t;
    unsigned v = (idx < NN) ? g_cnt[idx] : 0u;
    sh[t] = v;
    __syncthreads();
#pragma unroll
    for (int off = 1; off < 256; off <<= 1) {
        unsigned p = (t >= off) ? sh[t - off] : 0u;
        __syncthreads();
        sh[t] += p;
        __syncthreads();
    }
    if (idx < NN) g_off[idx] = sh[t] - v;            // local exclusive
    if (t == 255) g_bsum[blockIdx.x] = sh[255];
}

__global__ void scan_top_kernel() {
    __shared__ unsigned sh[256];
    int t = threadIdx.x;
    unsigned v = (t < NB) ? g_bsum[t] : 0u;
    sh[t] = v;
    __syncthreads();
#pragma unroll
    for (int off = 1; off < 256; off <<= 1) {
        unsigned p = (t >= off) ? sh[t - off] : 0u;
        __syncthreads();
        sh[t] += p;
        __syncthreads();
    }
    if (t < NB) g_bpre[t] = sh[t] - v;               // exclusive
}

__global__ void scan_add_kernel() {
    int idx = blockIdx.x * 256 + threadIdx.x;
    if (idx < NN) {
        unsigned o = g_off[idx] + g_bpre[blockIdx.x];
        g_off[idx] = o;
        g_cur[idx] = o;
    }
    if (idx == 0) g_off[NN] = EE;
}

// ---------------- CSR build: scatter edge sources ----------------------------
__global__ void scatter_kernel(const int* __restrict__ src,
                               const int* __restrict__ dst) {
    int e = blockIdx.x * blockDim.x + threadIdx.x;
    if (e >= EE) return;
    int d = dst[e];
    unsigned pos = atomicAdd(&g_cur[d], 1u);
    g_esrc[pos] = src[e];
}

// ---------------- fused softmax + aggregation: one warp per dst node ---------
// h gathered in fp16 (256B/edge); logits fp32; 2-edge software pipeline.
__global__ void __launch_bounds__(256) agg_kernel() {
    int gwarp = (blockIdx.x * 256 + threadIdx.x) >> 5;
    int l = threadIdx.x & 31;
    if (gwarp >= NN) return;
    const int d = gwarp;
    const int beg = (int)g_off[d], end = (int)g_off[d + 1];

    const float4 er4 = ((const float4*)g_er)[d];
    const int hh = l >> 3;                 // 8 lanes per head
    const float erc = sel4(er4, hh);

    float4 acc = make_float4(0.f, 0.f, 0.f, 0.f);
    float sumex = 0.f;
    const uint2* hmat = (const uint2*)g_hh;   // row = 32 uint2 (128 halves)

    int i = beg;
    for (; i + 1 < end; i += 2) {
        int s0 = __ldg(&g_esrc[i]);
        int s1 = __ldg(&g_esrc[i + 1]);
        float4 el0 = ((const float4*)g_el)[s0];
        float4 el1 = ((const float4*)g_el)[s1];
        uint2 u0 = hmat[s0 * 32 + l];
        uint2 u1 = hmat[s1 * 32 + l];

        float e0 = sel4(el0, hh) + erc;
        e0 = e0 > 0.f ? e0 : NEG_SLOPE * e0;
        float ex0 = __expf(e0);
        float e1 = sel4(el1, hh) + erc;
        e1 = e1 > 0.f ? e1 : NEG_SLOPE * e1;
        float ex1 = __expf(e1);
        sumex += ex0 + ex1;

        float2 a01 = __half22float2(*(__half2*)&u0.x);
        float2 a23 = __half22float2(*(__half2*)&u0.y);
        float2 b01 = __half22float2(*(__half2*)&u1.x);
        float2 b23 = __half22float2(*(__half2*)&u1.y);
        acc.x = fmaf(ex0, a01.x, fmaf(ex1, b01.x, acc.x));
        acc.y = fmaf(ex0, a01.y, fmaf(ex1, b01.y, acc.y));
        acc.z = fmaf(ex0, a23.x, fmaf(ex1, b23.x, acc.z));
        acc.w = fmaf(ex0, a23.y, fmaf(ex1, b23.y, acc.w));
    }
    if (i < end) {
        int s = __ldg(&g_esrc[i]);
        float4 el4 = ((const float4*)g_el)[s];
        uint2 u0 = hmat[s * 32 + l];
        float e = sel4(el4, hh) + erc;
        e = e > 0.f ? e : NEG_SLOPE * e;
        float ex = __expf(e);
        sumex += ex;
        float2 a01 = __half22float2(*(__half2*)&u0.x);
        float2 a23 = __half22float2(*(__half2*)&u0.y);
        acc.x = fmaf(ex, a01.x, acc.x);
        acc.y = fmaf(ex, a01.y, acc.y);
        acc.z = fmaf(ex, a23.x, acc.z);
        acc.w = fmaf(ex, a23.y, acc.w);
    }
    float inv = (sumex > 0.f) ? 1.f / sumex : 0.f;
    float4 o;
    o.x = acc.x * inv; o.y = acc.y * inv; o.z = acc.z * inv; o.w = acc.w * inv;
    ((float4*)g_rst)[d * 32 + l] = o;
}

// ---------------- BN stats ---------------------------------------------------
__global__ void bn_stats_kernel() {
    int c = threadIdx.x;                 // 128 threads = channels
    float s = 0.f, s2 = 0.f;
    for (int r = blockIdx.x; r < NN; r += gridDim.x) {
        float v = g_rst[r * HD + c];
        s += v; s2 += v * v;
    }
    atomicAdd(&g_sums[c], s);
    atomicAdd(&g_sumsq[c], s2);
}

// ---------------- BN normalize + ReLU (vectorized) ---------------------------
__global__ void bn_apply_kernel(const float* __restrict__ gamma,
                                const float* __restrict__ beta,
                                float* __restrict__ out)
{
    int i = blockIdx.x * blockDim.x + threadIdx.x;   // NN*HD/4 threads
    int c0 = (i * 4) & (HD - 1);
    const float inv_n = 1.f / (float)NN;
    float4 v = ((const float4*)g_rst)[i];
    float4 o;
#pragma unroll
    for (int j = 0; j < 4; j++) {
        int c = c0 + j;
        float mean = g_sums[c] * inv_n;
        float var  = g_sumsq[c] * inv_n - mean * mean;
        float vv = (j == 0) ? v.x : (j == 1) ? v.y : (j == 2) ? v.z : v.w;
        float y = gamma[c] * (vv - mean) * rsqrtf(var + BN_EPS) + beta[c];
        y = y > 0.f ? y : 0.f;
        if (j == 0) o.x = y; else if (j == 1) o.y = y;
        else if (j == 2) o.z = y; else o.w = y;
    }
    ((float4*)out)[i] = o;
}

// ---------------- launch -----------------------------------------------------
// NOTE: gemm_kernel kept as the 4th launch (ncu profiles #4).
extern "C" void kernel_launch(void* const* d_in, const int* in_sizes, int n_in,
                              void* d_out, int out_size)
{
    const float* x      = (const float*)d_in[0];
    const int*   src    = (const int*)d_in[1];
    const int*   dst    = (const int*)d_in[2];
    const float* W      = (const float*)d_in[3];
    const float* attn_l = (const float*)d_in[4];
    const float* attn_r = (const float*)d_in[5];
    // d_in[6] = bias: constant per-channel shift, cancels inside batch-norm
    const float* gamma  = (const float*)d_in[7];
    const float* beta   = (const float*)d_in[8];
    float* out = (float*)d_out;

    zero_kernel<<<(NN + 255) / 256, 256>>>();
    hist_kernel<<<(EE + 255) / 256, 256>>>(dst);
    scan_block_kernel<<<NB, 256>>>();
    gemm_kernel<<<(NN + 127) / 128, 256>>>(x, W, attn_l, attn_r);   // profiled
    scan_top_kernel<<<1, 256>>>();
    scan_add_kernel<<<NB, 256>>>();
    scatter_kernel<<<(EE + 255) / 256, 256>>>(src, dst);
    agg_kernel<<<(NN * 32 + 255) / 256, 256>>>();
    bn_stats_kernel<<<512, 128>>>();
    bn_apply_kernel<<<(NN * HD / 4 + 255) / 256, 256>>>(gamma, beta, out);
}